// round 10
// baseline (speedup 1.0000x reference)
#include <cuda_runtime.h>
#include <cuda_bf16.h>
#include <math.h>
#include <stdint.h>

// ---------------- problem constants ----------------
#define Bc   2
#define Tc   1024
#define Ec   2048
#define Hc   16
#define Gc   4
#define HSc  128
#define Lc   4
#define Vc   32000
#define FFc  8192
#define QKVc ((Hc + 2*Gc) * HSc)   // 3072
#define NTc  (Bc * Tc)             // 2048 tokens
#define EPSc 1e-5f

// ---------------- scratch (static device globals; no allocs) ----------------
__device__ float g_x  [(size_t)NTc * Ec];
__device__ float g_xn [(size_t)NTc * Ec];
__device__ float g_qkv[(size_t)NTc * QKVc];
__device__ float g_att[(size_t)NTc * Hc*HSc];
__device__ float g_ffh[(size_t)NTc * FFc];
// rounded-to-tf32 weight copies
__device__ float g_wqkv[(size_t)Lc * QKVc * Ec];
__device__ float g_wap [(size_t)Lc * Ec * Hc * HSc];
__device__ float g_wfc [(size_t)Lc * FFc * Ec];
__device__ float g_wmp [(size_t)Lc * Ec * FFc];
__device__ float g_wlm [(size_t)Vc * Ec];

// ---------------- tf32 round-to-nearest ----------------
__device__ __forceinline__ float to_tf32(float x) {
    uint32_t u;
    asm("cvt.rna.tf32.f32 %0, %1;" : "=r"(u) : "f"(x));
    return __uint_as_float(u);
}

__device__ __forceinline__ uint32_t smem_u32(const void* p) {
    uint32_t a;
    asm("{ .reg .u64 t; cvta.to.shared.u64 t, %1; cvt.u32.u64 %0, t; }" : "=r"(a) : "l"(p));
    return a;
}
__device__ __forceinline__ void cp16(uint32_t dst, const void* src) {
    asm volatile("cp.async.cg.shared.global [%0], [%1], 16;" :: "r"(dst), "l"(src));
}
__device__ __forceinline__ void ldsm4(uint32_t& r0, uint32_t& r1, uint32_t& r2, uint32_t& r3,
                                      uint32_t addr) {
    asm volatile("ldmatrix.sync.aligned.m8n8.x4.shared.b16 {%0,%1,%2,%3}, [%4];"
                 : "=r"(r0), "=r"(r1), "=r"(r2), "=r"(r3) : "r"(addr));
}
__device__ __forceinline__ void mma_tf32(float* d, uint32_t a0, uint32_t a1, uint32_t a2,
                                         uint32_t a3, uint32_t b0, uint32_t b1) {
    asm volatile(
        "mma.sync.aligned.m16n8k8.row.col.f32.tf32.tf32.f32 "
        "{%0,%1,%2,%3}, {%4,%5,%6,%7}, {%8,%9}, {%0,%1,%2,%3};"
        : "+f"(d[0]), "+f"(d[1]), "+f"(d[2]), "+f"(d[3])
        : "r"(a0), "r"(a1), "r"(a2), "r"(a3), "r"(b0), "r"(b1));
}
// 16B-granular XOR swizzle within a [rows][32 floats] tile (128B rows)
__device__ __forceinline__ uint32_t swz(uint32_t off) {
    return off ^ (((off >> 7) & 7) << 4);
}

// ---------------- gelu (tanh approx) ----------------
__device__ __forceinline__ float gelu_tanh(float x) {
    const float k0 = 0.7978845608028654f;
    float x3 = x * x * x;
    return 0.5f * x * (1.f + tanhf(k0 * (x + 0.044715f * x3)));
}

// =====================================================================
// tf32 mma.sync GEMM: C[M,N] = A[M,K] @ W[N,K]^T
// BM=BN=128, BK=32, 3-stage cp.async, 256 threads, warp grid 2x4,
// warp tile 64x32, fragment software pipelining, 1 barrier/chunk.
// EPI: 0 = store, 1 = C += (residual), 2 = gelu (+tf32 round),
//      3 = tf32 round, 4 = fused rope for qkv (+tf32 round)
// =====================================================================
#define GNS 3
#define GBM 128
#define GBN 128
#define GBK 32
#define STAGE_BYTES 32768           // 16KB A + 16KB B
#define GEMM_SMEM (GNS * STAGE_BYTES)   // 98304

template <int EPI>
__global__ void __launch_bounds__(256, 2) tc_gemm(const float* __restrict__ A,
                                                  const float* __restrict__ W,
                                                  float* __restrict__ C,
                                                  int M, int N, int K) {
    extern __shared__ char smem[];
    uint32_t sb = smem_u32(smem);
    int tid = threadIdx.x;
    int lane = tid & 31, wid = tid >> 5;
    int wm = wid & 1, wn = wid >> 1;            // 2x4 warp grid
    int m0 = blockIdx.y * GBM, n0 = blockIdx.x * GBN;
    int NC = K / GBK;

    const float* Ab = A + (size_t)m0 * K;
    const float* Wb = W + (size_t)n0 * K;

    float acc[4][4][4];
    #pragma unroll
    for (int i = 0; i < 4; i++)
        #pragma unroll
        for (int j = 0; j < 4; j++)
            #pragma unroll
            for (int r = 0; r < 4; r++) acc[i][j][r] = 0.f;

    int rowA = wm * 64 + (lane & 15);
    int khA  = lane >> 4;
    int rowB = wn * 32 + ((lane & 16) >> 1) + (lane & 7);
    int khB  = (lane >> 3) & 1;

    auto load_chunk = [&](int c) {
        int s = c % GNS;
        uint32_t as = sb + s * STAGE_BYTES;
        uint32_t bs = as + 16384;
        const float* Ac = Ab + c * GBK;
        const float* Wc = Wb + c * GBK;
        #pragma unroll
        for (int i = 0; i < 4; i++) {
            int t = tid + i * 256;
            int r = t >> 3, ch = t & 7;
            uint32_t off = (uint32_t)(r * 128) + (uint32_t)((ch ^ (r & 7)) * 16);
            cp16(as + off, Ac + (size_t)r * K + ch * 4);
            cp16(bs + off, Wc + (size_t)r * K + ch * 4);
        }
    };

    for (int c = 0; c < GNS - 1; c++) {
        load_chunk(c);
        asm volatile("cp.async.commit_group;" ::: "memory");
    }

    uint32_t af[2][4];
    uint32_t bf0[2][4], bf1[2][4];

    for (int c = 0; c < NC; c++) {
        asm volatile("cp.async.wait_group %0;" :: "n"(GNS - 2) : "memory");
        __syncthreads();

        if (c + GNS - 1 < NC) load_chunk(c + GNS - 1);
        asm volatile("cp.async.commit_group;" ::: "memory");

        uint32_t aBase = sb + (c % GNS) * STAGE_BYTES;
        uint32_t bBase = aBase + 16384;

        auto load_b = [&](int ks, int buf) {
            uint32_t r0, r1, r2, r3;
            ldsm4(r0, r1, r2, r3,
                  bBase + swz((uint32_t)(rowB * 128 + ks * 32 + khB * 16)));
            bf0[buf][0] = r0; bf1[buf][0] = r1; bf0[buf][1] = r2; bf1[buf][1] = r3;
            ldsm4(r0, r1, r2, r3,
                  bBase + swz((uint32_t)((rowB + 16) * 128 + ks * 32 + khB * 16)));
            bf0[buf][2] = r0; bf1[buf][2] = r1; bf0[buf][3] = r2; bf1[buf][3] = r3;
        };
        auto load_a = [&](int ks, int mt, int buf) {
            ldsm4(af[buf][0], af[buf][1], af[buf][2], af[buf][3],
                  aBase + swz((uint32_t)((rowA + mt * 16) * 128 + ks * 32 + khA * 16)));
        };

        load_b(0, 0);
        load_a(0, 0, 0);

        #pragma unroll
        for (int ks = 0; ks < 4; ks++) {
            if (ks < 3) load_b(ks + 1, (ks + 1) & 1);
            #pragma unroll
            for (int mt = 0; mt < 4; mt++) {
                if (mt < 3)       load_a(ks, mt + 1, (mt + 1) & 1);
                else if (ks < 3)  load_a(ks + 1, 0, 0);
                #pragma unroll
                for (int nt = 0; nt < 4; nt++)
                    mma_tf32(acc[mt][nt],
                             af[mt & 1][0], af[mt & 1][1], af[mt & 1][2], af[mt & 1][3],
                             bf0[ks & 1][nt], bf1[ks & 1][nt]);
            }
        }
    }

    int gr = lane >> 2, gc2 = (lane & 3) * 2;

    if (EPI == 4) {
        // ---- fused rope epilogue (qkv GEMM; BN=128 == one head per n-block) ----
        float* st = (float*)smem;            // 64KB tile stage (reuses cp.async stages)
        __syncthreads();                     // all warps done with mainloop smem
        #pragma unroll
        for (int mt = 0; mt < 4; mt++) {
            int rl = wm * 64 + mt * 16 + gr;
            #pragma unroll
            for (int nt = 0; nt < 4; nt++) {
                int cl = wn * 32 + nt * 8 + gc2;
                *(float2*)&st[rl * 128 + cl] =
                    make_float2(acc[mt][nt][0], acc[mt][nt][1]);
                *(float2*)&st[(rl + 8) * 128 + cl] =
                    make_float2(acc[mt][nt][2], acc[mt][nt][3]);
            }
        }
        __syncthreads();
        int head = n0 >> 7;
        bool isv = (head >= Hc + Gc);
        const float kf = 0.20762050593046f;  // log2(10000)/64
        #pragma unroll
        for (int e = 0; e < 32; e++) {
            int idx = tid + e * 256;         // 8192 (row, freq) pairs
            int r = idx >> 6, i = idx & 63;
            float x1 = st[r * 128 + i];
            float x2 = st[r * 128 + i + 64];
            float o1, o2;
            if (isv) {
                o1 = x1; o2 = x2;
            } else {
                int t = (m0 + r) & (Tc - 1);
                float ang = (float)t * exp2f(-(float)i * kf);
                float sn, cs;
                sincosf(ang, &sn, &cs);
                o1 = x1 * cs - x2 * sn;
                o2 = x2 * cs + x1 * sn;
            }
            float* crow = C + (size_t)(m0 + r) * N + n0;
            crow[i]      = to_tf32(o1);
            crow[i + 64] = to_tf32(o2);
        }
        return;
    }

    // ---- standard epilogues ----
    #pragma unroll
    for (int mt = 0; mt < 4; mt++) {
        int r0 = m0 + wm * 64 + mt * 16 + gr;
        #pragma unroll
        for (int nt = 0; nt < 4; nt++) {
            int cc = n0 + wn * 32 + nt * 8 + gc2;
            float* p0 = C + (size_t)r0 * N + cc;
            float* p1 = p0 + (size_t)8 * N;
            float v0 = acc[mt][nt][0], v1 = acc[mt][nt][1];
            float v2 = acc[mt][nt][2], v3 = acc[mt][nt][3];
            if (EPI == 1) {
                float2 o0 = *(float2*)p0, o1 = *(float2*)p1;
                v0 += o0.x; v1 += o0.y; v2 += o1.x; v3 += o1.y;
            }
            if (EPI == 2) {
                v0 = to_tf32(gelu_tanh(v0)); v1 = to_tf32(gelu_tanh(v1));
                v2 = to_tf32(gelu_tanh(v2)); v3 = to_tf32(gelu_tanh(v3));
            }
            if (EPI == 3) {
                v0 = to_tf32(v0); v1 = to_tf32(v1);
                v2 = to_tf32(v2); v3 = to_tf32(v3);
            }
            *(float2*)p0 = make_float2(v0, v1);
            *(float2*)p1 = make_float2(v2, v3);
        }
    }
}

// =====================================================================
// Flash attention, tf32 mma.sync. CTA = (128 q-rows, head, batch).
// 256 threads, warp grid 2x4. K-tiles of 64 keys. Online softmax.
// smem: Q 64K | K 32K | VT 32K | P 32K | stats ~3K  = 166912 B
// =====================================================================
#define FAQ_OFF 0
#define FAK_OFF 65536
#define FAV_OFF 98304
#define FAP_OFF 131072
#define FAM_OFF 163840
#define FAL_OFF 164352
#define FAR_OFF 164864
#define FA_SMEM 166912

__global__ void __launch_bounds__(256) fattn_kernel(const float* __restrict__ qkv,
                                                    float* __restrict__ y) {
    extern __shared__ char smem[];
    uint32_t sb = smem_u32(smem);
    float* ms  = (float*)(smem + FAM_OFF);
    float* ls  = (float*)(smem + FAL_OFF);
    float* red = (float*)(smem + FAR_OFF);

    int qt = (int)gridDim.x - 1 - (int)blockIdx.x;   // big tiles first
    int h = blockIdx.y, b = blockIdx.z;
    int g = h >> 2;
    int q0 = qt * 128;
    int tid = threadIdx.x, lane = tid & 31, wid = tid >> 5;
    int wm = wid & 1, wn = wid >> 1;
    int gr = lane >> 2, gc2 = (lane & 3) * 2;
    const float scale = 0.08838834764831845f;

    const float* qbase = qkv + (size_t)(b * Tc) * QKVc + h * HSc;
    const float* kbase = qkv + (size_t)(b * Tc) * QKVc + (Hc + g) * HSc;
    const float* vbase = qkv + (size_t)(b * Tc) * QKVc + (Hc + Gc + g) * HSc;

    // ---- load Q tile (128 x 128 f32) into 4 k-subtiles ----
    #pragma unroll
    for (int i = 0; i < 16; i++) {
        int t = tid + i * 256;
        int r = t >> 5, ch = t & 31;
        int ksub = ch >> 3, within = ch & 7;
        cp16(sb + FAQ_OFF + ksub * 16384 + swz((uint32_t)(r * 128 + within * 16)),
             qbase + (size_t)(q0 + r) * QKVc + ch * 4);
    }
    asm volatile("cp.async.commit_group;" ::: "memory");

    if (tid < 128) { ms[tid] = -1e30f; ls[tid] = 0.f; }

    float oacc[4][4][4];
    #pragma unroll
    for (int i = 0; i < 4; i++)
        #pragma unroll
        for (int j = 0; j < 4; j++)
            #pragma unroll
            for (int r = 0; r < 4; r++) oacc[i][j][r] = 0.f;

    int rowA  = wm * 64 + (lane & 15);
    int khA   = lane >> 4;
    int rowBs = wn * 16 + ((lane & 16) >> 1) + (lane & 7);   // S-phase (n span 16)
    int rowBp = wn * 32 + ((lane & 16) >> 1) + (lane & 7);   // PV-phase (n span 32)
    int khB   = (lane >> 3) & 1;

    int nkt = 2 * qt + 2;
    for (int kt = 0; kt < nkt; kt++) {
        int s0 = kt * 64;
        if (kt > 0) __syncthreads();   // prior tile's PV ldsm done before overwrite

        // ---- load K tile (64 x 128) via cp.async ----
        #pragma unroll
        for (int i = 0; i < 8; i++) {
            int t = tid + i * 256;
            int r = t >> 5, ch = t & 31;
            int ksub = ch >> 3, within = ch & 7;
            cp16(sb + FAK_OFF + ksub * 8192 + swz((uint32_t)(r * 128 + within * 16)),
                 kbase + (size_t)(s0 + r) * QKVc + ch * 4);
        }
        asm volatile("cp.async.commit_group;" ::: "memory");

        // ---- load + transpose V tile: VT[j][s], 2 s-subtiles of [128][32] ----
        {
            int s = tid >> 2;            // 0..63
            int jc = (tid & 3) * 32;
            int ssub = s >> 5, swi = s & 31;
            const float* vr = vbase + (size_t)(s0 + s) * QKVc + jc;
            #pragma unroll
            for (int i = 0; i < 8; i++) {
                float4 v4 = *(const float4*)(vr + i * 4);
                int j = jc + i * 4;
                char* base = smem + FAV_OFF + ssub * 16384;
                *(float*)(base + swz((uint32_t)((j    ) * 128 + swi * 4))) = v4.x;
                *(float*)(base + swz((uint32_t)((j + 1) * 128 + swi * 4))) = v4.y;
                *(float*)(base + swz((uint32_t)((j + 2) * 128 + swi * 4))) = v4.z;
                *(float*)(base + swz((uint32_t)((j + 3) * 128 + swi * 4))) = v4.w;
            }
        }
        asm volatile("cp.async.wait_group 0;" ::: "memory");
        __syncthreads();

        // ---- S = Q K^T (128 x 64), warp tile 64x16 ----
        float sacc[4][2][4];
        #pragma unroll
        for (int i = 0; i < 4; i++)
            #pragma unroll
            for (int j = 0; j < 2; j++)
                #pragma unroll
                for (int r = 0; r < 4; r++) sacc[i][j][r] = 0.f;

        #pragma unroll
        for (int ks = 0; ks < 16; ks++) {
            uint32_t bqk0, bqk1, bqk2, bqk3;
            ldsm4(bqk0, bqk1, bqk2, bqk3,
                  sb + FAK_OFF + (ks >> 2) * 8192 +
                  swz((uint32_t)(rowBs * 128 + (ks & 3) * 32 + khB * 16)));
            #pragma unroll
            for (int mt = 0; mt < 4; mt++) {
                uint32_t a0, a1, a2, a3;
                ldsm4(a0, a1, a2, a3,
                      sb + FAQ_OFF + (ks >> 2) * 16384 +
                      swz((uint32_t)((rowA + mt * 16) * 128 + (ks & 3) * 32 + khA * 16)));
                mma_tf32(sacc[mt][0], a0, a1, a2, a3, bqk0, bqk1);
                mma_tf32(sacc[mt][1], a0, a1, a2, a3, bqk2, bqk3);
            }
        }

        // ---- scale + causal mask ----
        bool diag = (s0 >= q0);
        #pragma unroll
        for (int mt = 0; mt < 4; mt++)
            #pragma unroll
            for (int nt = 0; nt < 2; nt++)
                #pragma unroll
                for (int idx = 0; idx < 4; idx++) {
                    float v = sacc[mt][nt][idx] * scale;
                    if (diag) {
                        int rg = q0 + wm * 64 + mt * 16 + gr + ((idx >> 1) << 3);
                        int sg = s0 + wn * 16 + nt * 8 + gc2 + (idx & 1);
                        if (sg > rg) v = -1e30f;
                    }
                    sacc[mt][nt][idx] = v;
                }

        // ---- row max reduce ----
        #pragma unroll
        for (int mt = 0; mt < 4; mt++)
            #pragma unroll
            for (int hh = 0; hh < 2; hh++) {
                float mx = fmaxf(fmaxf(sacc[mt][0][hh * 2], sacc[mt][0][hh * 2 + 1]),
                                 fmaxf(sacc[mt][1][hh * 2], sacc[mt][1][hh * 2 + 1]));
                mx = fmaxf(mx, __shfl_xor_sync(0xffffffffu, mx, 1));
                mx = fmaxf(mx, __shfl_xor_sync(0xffffffffu, mx, 2));
                if ((lane & 3) == 0)
                    red[wn * 128 + wm * 64 + mt * 16 + gr + hh * 8] = mx;
            }
        __syncthreads();

        float mnewr[4][2], alpha[4][2], psum[4][2];
        #pragma unroll
        for (int mt = 0; mt < 4; mt++)
            #pragma unroll
            for (int hh = 0; hh < 2; hh++) {
                int r = wm * 64 + mt * 16 + gr + hh * 8;
                float tmax = fmaxf(fmaxf(red[r], red[128 + r]),
                                   fmaxf(red[256 + r], red[384 + r]));
                float mold = ms[r];
                float mnew = fmaxf(mold, tmax);
                mnewr[mt][hh] = mnew;
                alpha[mt][hh] = expf(mold - mnew);
                float p0 = expf(sacc[mt][0][hh * 2]     - mnew);
                float p1 = expf(sacc[mt][0][hh * 2 + 1] - mnew);
                float p2 = expf(sacc[mt][1][hh * 2]     - mnew);
                float p3 = expf(sacc[mt][1][hh * 2 + 1] - mnew);
                sacc[mt][0][hh * 2]     = p0; sacc[mt][0][hh * 2 + 1] = p1;
                sacc[mt][1][hh * 2]     = p2; sacc[mt][1][hh * 2 + 1] = p3;
                float ps = p0 + p1 + p2 + p3;
                ps += __shfl_xor_sync(0xffffffffu, ps, 1);
                ps += __shfl_xor_sync(0xffffffffu, ps, 2);
                psum[mt][hh] = ps;
            }
        __syncthreads();   // all reads of red done before overwrite
        #pragma unroll
        for (int mt = 0; mt < 4; mt++)
            #pragma unroll
            for (int hh = 0; hh < 2; hh++)
                if ((lane & 3) == 0)
                    red[wn * 128 + wm * 64 + mt * 16 + gr + hh * 8] = psum[mt][hh];
        __syncthreads();
        #pragma unroll
        for (int mt = 0; mt < 4; mt++)
            #pragma unroll
            for (int hh = 0; hh < 2; hh++) {
                int r = wm * 64 + mt * 16 + gr + hh * 8;
                float pt = red[r] + red[128 + r] + red[256 + r] + red[384 + r];
                float lnew = ls[r] * alpha[mt][hh] + pt;
                if (wn == 0 && (lane & 3) == 0) { ms[r] = mnewr[mt][hh]; ls[r] = lnew; }
            }

        // ---- store P (tf32) to smem; rescale O ----
        #pragma unroll
        for (int mt = 0; mt < 4; mt++)
            #pragma unroll
            for (int nt = 0; nt < 2; nt++) {
                int c = wn * 16 + nt * 8 + gc2;
                int ssub = c >> 5, cw = c & 31;
                int r0l = wm * 64 + mt * 16 + gr;
                char* base = smem + FAP_OFF + ssub * 16384;
                *(float2*)(base + swz((uint32_t)(r0l * 128 + cw * 4))) =
                    make_float2(to_tf32(sacc[mt][nt][0]), to_tf32(sacc[mt][nt][1]));
                *(float2*)(base + swz((uint32_t)((r0l + 8) * 128 + cw * 4))) =
                    make_float2(to_tf32(sacc[mt][nt][2]), to_tf32(sacc[mt][nt][3]));
            }
        #pragma unroll
        for (int mt = 0; mt < 4; mt++)
            #pragma unroll
            for (int nt = 0; nt < 4; nt++) {
                oacc[mt][nt][0] *= alpha[mt][0];
                oacc[mt][nt][1] *= alpha[mt][0];
                oacc[mt][nt][2] *= alpha[mt][1];
                oacc[mt][nt][3] *= alpha[mt][1];
            }
        __syncthreads();   // P visible to all warps

        // ---- O += P V  (P 128x64, V^T in smem) ----
        #pragma unroll
        for (int ks = 0; ks < 8; ks++) {
            uint32_t vb0[4], vb1[4];
            {
                uint32_t r0, r1, r2, r3;
                ldsm4(r0, r1, r2, r3,
                      sb + FAV_OFF + (ks >> 2) * 16384 +
                      swz((uint32_t)(rowBp * 128 + (ks & 3) * 32 + khB * 16)));
                vb0[0] = r0; vb1[0] = r1; vb0[1] = r2; vb1[1] = r3;
                ldsm4(r0, r1, r2, r3,
                      sb + FAV_OFF + (ks >> 2) * 16384 +
                      swz((uint32_t)((rowBp + 16) * 128 + (ks & 3) * 32 + khB * 16)));
                vb0[2] = r0; vb1[2] = r1; vb0[3] = r2; vb1[3] = r3;
            }
            #pragma unroll
            for (int mt = 0; mt < 4; mt++) {
                uint32_t a0, a1, a2, a3;
                ldsm4(a0, a1, a2, a3,
                      sb + FAP_OFF + (ks >> 2) * 16384 +
                      swz((uint32_t)((rowA + mt * 16) * 128 + (ks & 3) * 32 + khA * 16)));
                #pragma unroll
                for (int nt = 0; nt < 4; nt++)
                    mma_tf32(oacc[mt][nt], a0, a1, a2, a3, vb0[nt], vb1[nt]);
            }
        }
    }

    __syncthreads();   // final ls visible
    #pragma unroll
    for (int mt = 0; mt < 4; mt++) {
        int rl = wm * 64 + mt * 16 + gr;
        float i0 = 1.f / ls[rl];
        float i1 = 1.f / ls[rl + 8];
        int rg = q0 + rl;
        #pragma unroll
        for (int nt = 0; nt < 4; nt++) {
            int j = h * HSc + wn * 32 + nt * 8 + gc2;
            *(float2*)&y[(size_t)(b * Tc + rg) * (Hc * HSc) + j] =
                make_float2(to_tf32(oacc[mt][nt][0] * i0), to_tf32(oacc[mt][nt][1] * i0));
            *(float2*)&y[(size_t)(b * Tc + rg + 8) * (Hc * HSc) + j] =
                make_float2(to_tf32(oacc[mt][nt][2] * i1), to_tf32(oacc[mt][nt][3] * i1));
        }
    }
}

// ---------------- weight round-to-tf32 (two arrays per launch) ----------------
__global__ void round_w2_kernel(const float* __restrict__ in1, float* __restrict__ out1, size_t n1,
                                const float* __restrict__ in2, float* __restrict__ out2, size_t n2) {
    size_t i = (size_t)blockIdx.x * blockDim.x + threadIdx.x;
    const float* in; float* out; size_t j;
    if (i < n1) { in = in1; out = out1; j = i; }
    else if (i < n1 + n2) { in = in2; out = out2; j = i - n1; }
    else return;
    float4 v = ((const float4*)in)[j];
    v.x = to_tf32(v.x); v.y = to_tf32(v.y); v.z = to_tf32(v.z); v.w = to_tf32(v.w);
    ((float4*)out)[j] = v;
}

__global__ void round_w_kernel(const float* __restrict__ in, float* __restrict__ out, size_t n4) {
    size_t i = (size_t)blockIdx.x * blockDim.x + threadIdx.x;
    if (i < n4) {
        float4 v = ((const float4*)in)[i];
        v.x = to_tf32(v.x); v.y = to_tf32(v.y); v.z = to_tf32(v.z); v.w = to_tf32(v.w);
        ((float4*)out)[i] = v;
    }
}

// ---------------- embed ----------------
__global__ void embed_kernel(const int* __restrict__ idx,
                             const float* __restrict__ wte,
                             float* __restrict__ x) {
    size_t i = (size_t)blockIdx.x * blockDim.x + threadIdx.x;
    if (i < (size_t)NTc * Ec) {
        int tok = (int)(i / Ec);
        int e   = (int)(i % Ec);
        x[i] = wte[(size_t)idx[tok] * Ec + e];
    }
}

// ---------------- rmsnorm (block per token, float4), output rounded to tf32 ------
__global__ void __launch_bounds__(256) rmsnorm_kernel(const float* __restrict__ x,
                                                      const float* __restrict__ w,
                                                      float* __restrict__ out) {
    int t = blockIdx.x;
    const float4* xr = (const float4*)(x + (size_t)t * Ec);
    const float4* wr = (const float4*)w;
    float4* orow = (float4*)(out + (size_t)t * Ec);
    float4 xv[2], wv[2];
    float s = 0.f;
    #pragma unroll
    for (int i = 0; i < 2; i++) {
        xv[i] = xr[threadIdx.x + i * 256];
        wv[i] = wr[threadIdx.x + i * 256];
        s += xv[i].x * xv[i].x + xv[i].y * xv[i].y + xv[i].z * xv[i].z + xv[i].w * xv[i].w;
    }
    __shared__ float sh[8];
    int lane = threadIdx.x & 31, warp = threadIdx.x >> 5;
    #pragma unroll
    for (int o = 16; o > 0; o >>= 1) s += __shfl_xor_sync(0xffffffffu, s, o);
    if (lane == 0) sh[warp] = s;
    __syncthreads();
    float tot = sh[0] + sh[1] + sh[2] + sh[3] + sh[4] + sh[5] + sh[6] + sh[7];
    float inv = rsqrtf(tot / (float)Ec + EPSc);
    #pragma unroll
    for (int i = 0; i < 2; i++) {
        float4 o;
        o.x = to_tf32(xv[i].x * inv * wv[i].x);
        o.y = to_tf32(xv[i].y * inv * wv[i].y);
        o.z = to_tf32(xv[i].z * inv * wv[i].z);
        o.w = to_tf32(xv[i].w * inv * wv[i].w);
        orow[threadIdx.x + i * 256] = o;
    }
}

// ---------------- launcher ----------------
static void launch_gemm(int epi, const float* A, const float* W, float* C,
                        int M, int N, int K) {
    dim3 grid(N / GBN, M / GBM);
    if (epi == 0)      tc_gemm<0><<<grid, 256, GEMM_SMEM>>>(A, W, C, M, N, K);
    else if (epi == 1) tc_gemm<1><<<grid, 256, GEMM_SMEM>>>(A, W, C, M, N, K);
    else if (epi == 2) tc_gemm<2><<<grid, 256, GEMM_SMEM>>>(A, W, C, M, N, K);
    else if (epi == 3) tc_gemm<3><<<grid, 256, GEMM_SMEM>>>(A, W, C, M, N, K);
    else               tc_gemm<4><<<grid, 256, GEMM_SMEM>>>(A, W, C, M, N, K);
}

extern "C" void kernel_launch(void* const* d_in, const int* in_sizes, int n_in,
                              void* d_out, int out_size) {
    const int*   idx  = (const int*)  d_in[0];
    const float* wte  = (const float*)d_in[1];
    const float* qkvw = (const float*)d_in[2];
    const float* apw  = (const float*)d_in[3];
    const float* fcw  = (const float*)d_in[4];
    const float* mpw  = (const float*)d_in[5];
    const float* n1w  = (const float*)d_in[6];
    const float* n2w  = (const float*)d_in[7];
    const float* lnfw = (const float*)d_in[8];
    const float* lmw  = (const float*)d_in[9];
    float* out = (float*)d_out;
    (void)in_sizes; (void)n_in; (void)out_size;

    float *x, *xn, *qkv, *att, *ffh;
    float *wq, *wa, *wf, *wm, *wl;
    cudaGetSymbolAddress((void**)&x,   g_x);
    cudaGetSymbolAddress((void**)&xn,  g_xn);
    cudaGetSymbolAddress((void**)&qkv, g_qkv);
    cudaGetSymbolAddress((void**)&att, g_att);
    cudaGetSymbolAddress((void**)&ffh, g_ffh);
    cudaGetSymbolAddress((void**)&wq,  g_wqkv);
    cudaGetSymbolAddress((void**)&wa,  g_wap);
    cudaGetSymbolAddress((void**)&wf,  g_wfc);
    cudaGetSymbolAddress((void**)&wm,  g_wmp);
    cudaGetSymbolAddress((void**)&wl,  g_wlm);

    cudaFuncSetAttribute(tc_gemm<0>, cudaFuncAttributeMaxDynamicSharedMemorySize, GEMM_SMEM);
    cudaFuncSetAttribute(tc_gemm<1>, cudaFuncAttributeMaxDynamicSharedMemorySize, GEMM_SMEM);
    cudaFuncSetAttribute(tc_gemm<2>, cudaFuncAttributeMaxDynamicSharedMemorySize, GEMM_SMEM);
    cudaFuncSetAttribute(tc_gemm<3>, cudaFuncAttributeMaxDynamicSharedMemorySize, GEMM_SMEM);
    cudaFuncSetAttribute(tc_gemm<4>, cudaFuncAttributeMaxDynamicSharedMemorySize, GEMM_SMEM);
    cudaFuncSetAttribute(fattn_kernel, cudaFuncAttributeMaxDynamicSharedMemorySize, FA_SMEM);

    // weight rounding
    {
        size_t n1 = (size_t)Lc * QKVc * Ec / 4;
        size_t n2 = (size_t)Lc * Ec * Hc * HSc / 4;
        round_w2_kernel<<<(unsigned)((n1 + n2 + 255) / 256), 256>>>(qkvw, wq, n1, apw, wa, n2);
        size_t n3 = (size_t)Lc * FFc * Ec / 4;
        size_t n4 = (size_t)Lc * Ec * FFc / 4;
        round_w2_kernel<<<(unsigned)((n3 + n4 + 255) / 256), 256>>>(fcw, wf, n3, mpw, wm, n4);
        size_t n5 = (size_t)Vc * Ec / 4;
        round_w_kernel<<<(unsigned)((n5 + 255) / 256), 256>>>(lmw, wl, n5);
    }

    embed_kernel<<<((size_t)NTc * Ec + 255) / 256, 256>>>(idx, wte, x);

    for (int l = 0; l < Lc; l++) {
        rmsnorm_kernel<<<NTc, 256>>>(x, n1w + (size_t)l * Ec, xn);
        launch_gemm(4, xn, wq + (size_t)l * QKVc * Ec, qkv, NTc, QKVc, Ec);  // fused rope
        fattn_kernel<<<dim3(Tc / 128, Hc, Bc), 256, FA_SMEM>>>(qkv, att);
        launch_gemm(1, att, wa + (size_t)l * Ec * (Hc * HSc), x, NTc, Ec, Hc * HSc);
        rmsnorm_kernel<<<NTc, 256>>>(x, n2w + (size_t)l * Ec, xn);
        launch_gemm(2, xn, wf + (size_t)l * FFc * Ec, ffh, NTc, FFc, Ec);
        launch_gemm(1, ffh, wm + (size_t)l * Ec * FFc, x, NTc, Ec, FFc);
    }

    rmsnorm_kernel<<<NTc, 256>>>(x, lnfw, xn);
    launch_gemm(0, xn, wl, out, NTc, Vc, Ec);
}

// round 11
// speedup vs baseline: 1.0008x; 1.0008x over previous
#include <cuda_runtime.h>
#include <cuda_bf16.h>
#include <math.h>
#include <stdint.h>

// ---------------- problem constants ----------------
#define Bc   2
#define Tc   1024
#define Ec   2048
#define Hc   16
#define Gc   4
#define HSc  128
#define Lc   4
#define Vc   32000
#define FFc  8192
#define QKVc ((Hc + 2*Gc) * HSc)   // 3072
#define NTc  (Bc * Tc)             // 2048 tokens
#define EPSc 1e-5f

// ---------------- scratch (static device globals; no allocs) ----------------
__device__ float g_x  [(size_t)NTc * Ec];
__device__ float g_xn [(size_t)NTc * Ec];
__device__ float g_qkv[(size_t)NTc * QKVc];
__device__ float g_att[(size_t)NTc * Hc*HSc];
__device__ float g_ffh[(size_t)NTc * FFc];
// rounded-to-tf32 weight copies
__device__ float g_wqkv[(size_t)Lc * QKVc * Ec];
__device__ float g_wap [(size_t)Lc * Ec * Hc * HSc];
__device__ float g_wfc [(size_t)Lc * FFc * Ec];
__device__ float g_wmp [(size_t)Lc * Ec * FFc];
__device__ float g_wlm [(size_t)Vc * Ec];

// ---------------- tf32 round-to-nearest ----------------
__device__ __forceinline__ float to_tf32(float x) {
    uint32_t u;
    asm("cvt.rna.tf32.f32 %0, %1;" : "=r"(u) : "f"(x));
    return __uint_as_float(u);
}

__device__ __forceinline__ uint32_t smem_u32(const void* p) {
    uint32_t a;
    asm("{ .reg .u64 t; cvta.to.shared.u64 t, %1; cvt.u32.u64 %0, t; }" : "=r"(a) : "l"(p));
    return a;
}
__device__ __forceinline__ void cp16(uint32_t dst, const void* src) {
    asm volatile("cp.async.cg.shared.global [%0], [%1], 16;" :: "r"(dst), "l"(src));
}
__device__ __forceinline__ void ldsm4(uint32_t& r0, uint32_t& r1, uint32_t& r2, uint32_t& r3,
                                      uint32_t addr) {
    asm volatile("ldmatrix.sync.aligned.m8n8.x4.shared.b16 {%0,%1,%2,%3}, [%4];"
                 : "=r"(r0), "=r"(r1), "=r"(r2), "=r"(r3) : "r"(addr));
}
__device__ __forceinline__ void mma_tf32(float* d, uint32_t a0, uint32_t a1, uint32_t a2,
                                         uint32_t a3, uint32_t b0, uint32_t b1) {
    asm volatile(
        "mma.sync.aligned.m16n8k8.row.col.f32.tf32.tf32.f32 "
        "{%0,%1,%2,%3}, {%4,%5,%6,%7}, {%8,%9}, {%0,%1,%2,%3};"
        : "+f"(d[0]), "+f"(d[1]), "+f"(d[2]), "+f"(d[3])
        : "r"(a0), "r"(a1), "r"(a2), "r"(a3), "r"(b0), "r"(b1));
}
// 16B-granular XOR swizzle within a [rows][32 floats] tile (128B rows)
__device__ __forceinline__ uint32_t swz(uint32_t off) {
    return off ^ (((off >> 7) & 7) << 4);
}

// ---------------- gelu (tanh approx) ----------------
__device__ __forceinline__ float gelu_tanh(float x) {
    const float k0 = 0.7978845608028654f;
    float x3 = x * x * x;
    return 0.5f * x * (1.f + tanhf(k0 * (x + 0.044715f * x3)));
}

// =====================================================================
// tf32 mma.sync GEMM: C[M,N] = A[M,K] @ W[N,K]^T
// BM=BN=128, BK=32, 3-stage cp.async, 256 threads, warp grid 2x4,
// warp tile 64x32, fragment software pipelining, 1 barrier/chunk.
// EPI: 0 = store, 1 = C += (residual), 2 = gelu (+tf32 round),
//      3 = tf32 round, 4 = fused rope for qkv (+tf32 round)
// =====================================================================
#define GNS 3
#define GBM 128
#define GBN 128
#define GBK 32
#define STAGE_BYTES 32768           // 16KB A + 16KB B
#define GEMM_SMEM (GNS * STAGE_BYTES)   // 98304

template <int EPI>
__global__ void __launch_bounds__(256, 2) tc_gemm(const float* __restrict__ A,
                                                  const float* __restrict__ W,
                                                  float* __restrict__ C,
                                                  int M, int N, int K) {
    extern __shared__ char smem[];
    uint32_t sb = smem_u32(smem);
    int tid = threadIdx.x;
    int lane = tid & 31, wid = tid >> 5;
    int wm = wid & 1, wn = wid >> 1;            // 2x4 warp grid
    int m0 = blockIdx.y * GBM, n0 = blockIdx.x * GBN;
    int NC = K / GBK;

    const float* Ab = A + (size_t)m0 * K;
    const float* Wb = W + (size_t)n0 * K;

    float acc[4][4][4];
    #pragma unroll
    for (int i = 0; i < 4; i++)
        #pragma unroll
        for (int j = 0; j < 4; j++)
            #pragma unroll
            for (int r = 0; r < 4; r++) acc[i][j][r] = 0.f;

    int rowA = wm * 64 + (lane & 15);
    int khA  = lane >> 4;
    int rowB = wn * 32 + ((lane & 16) >> 1) + (lane & 7);
    int khB  = (lane >> 3) & 1;

    auto load_chunk = [&](int c) {
        int s = c % GNS;
        uint32_t as = sb + s * STAGE_BYTES;
        uint32_t bs = as + 16384;
        const float* Ac = Ab + c * GBK;
        const float* Wc = Wb + c * GBK;
        #pragma unroll
        for (int i = 0; i < 4; i++) {
            int t = tid + i * 256;
            int r = t >> 3, ch = t & 7;
            uint32_t off = (uint32_t)(r * 128) + (uint32_t)((ch ^ (r & 7)) * 16);
            cp16(as + off, Ac + (size_t)r * K + ch * 4);
            cp16(bs + off, Wc + (size_t)r * K + ch * 4);
        }
    };

    for (int c = 0; c < GNS - 1; c++) {
        load_chunk(c);
        asm volatile("cp.async.commit_group;" ::: "memory");
    }

    uint32_t af[2][4];
    uint32_t bf0[2][4], bf1[2][4];

    for (int c = 0; c < NC; c++) {
        asm volatile("cp.async.wait_group %0;" :: "n"(GNS - 2) : "memory");
        __syncthreads();

        if (c + GNS - 1 < NC) load_chunk(c + GNS - 1);
        asm volatile("cp.async.commit_group;" ::: "memory");

        uint32_t aBase = sb + (c % GNS) * STAGE_BYTES;
        uint32_t bBase = aBase + 16384;

        auto load_b = [&](int ks, int buf) {
            uint32_t r0, r1, r2, r3;
            ldsm4(r0, r1, r2, r3,
                  bBase + swz((uint32_t)(rowB * 128 + ks * 32 + khB * 16)));
            bf0[buf][0] = r0; bf1[buf][0] = r1; bf0[buf][1] = r2; bf1[buf][1] = r3;
            ldsm4(r0, r1, r2, r3,
                  bBase + swz((uint32_t)((rowB + 16) * 128 + ks * 32 + khB * 16)));
            bf0[buf][2] = r0; bf1[buf][2] = r1; bf0[buf][3] = r2; bf1[buf][3] = r3;
        };
        auto load_a = [&](int ks, int mt, int buf) {
            ldsm4(af[buf][0], af[buf][1], af[buf][2], af[buf][3],
                  aBase + swz((uint32_t)((rowA + mt * 16) * 128 + ks * 32 + khA * 16)));
        };

        load_b(0, 0);
        load_a(0, 0, 0);

        #pragma unroll
        for (int ks = 0; ks < 4; ks++) {
            if (ks < 3) load_b(ks + 1, (ks + 1) & 1);
            #pragma unroll
            for (int mt = 0; mt < 4; mt++) {
                if (mt < 3)       load_a(ks, mt + 1, (mt + 1) & 1);
                else if (ks < 3)  load_a(ks + 1, 0, 0);
                #pragma unroll
                for (int nt = 0; nt < 4; nt++)
                    mma_tf32(acc[mt][nt],
                             af[mt & 1][0], af[mt & 1][1], af[mt & 1][2], af[mt & 1][3],
                             bf0[ks & 1][nt], bf1[ks & 1][nt]);
            }
        }
    }

    int gr = lane >> 2, gc2 = (lane & 3) * 2;

    if (EPI == 4) {
        // ---- fused rope epilogue (qkv GEMM; BN=128 == one head per n-block) ----
        float* st = (float*)smem;            // 64KB tile stage (reuses cp.async stages)
        __syncthreads();                     // all warps done with mainloop smem
        #pragma unroll
        for (int mt = 0; mt < 4; mt++) {
            int rl = wm * 64 + mt * 16 + gr;
            #pragma unroll
            for (int nt = 0; nt < 4; nt++) {
                int cl = wn * 32 + nt * 8 + gc2;
                *(float2*)&st[rl * 128 + cl] =
                    make_float2(acc[mt][nt][0], acc[mt][nt][1]);
                *(float2*)&st[(rl + 8) * 128 + cl] =
                    make_float2(acc[mt][nt][2], acc[mt][nt][3]);
            }
        }
        __syncthreads();
        int head = n0 >> 7;
        bool isv = (head >= Hc + Gc);
        const float kf = 0.20762050593046f;  // log2(10000)/64
        #pragma unroll
        for (int e = 0; e < 32; e++) {
            int idx = tid + e * 256;         // 8192 (row, freq) pairs
            int r = idx >> 6, i = idx & 63;
            float x1 = st[r * 128 + i];
            float x2 = st[r * 128 + i + 64];
            float o1, o2;
            if (isv) {
                o1 = x1; o2 = x2;
            } else {
                int t = (m0 + r) & (Tc - 1);
                float ang = (float)t * exp2f(-(float)i * kf);
                float sn, cs;
                sincosf(ang, &sn, &cs);
                o1 = x1 * cs - x2 * sn;
                o2 = x2 * cs + x1 * sn;
            }
            float* crow = C + (size_t)(m0 + r) * N + n0;
            crow[i]      = to_tf32(o1);
            crow[i + 64] = to_tf32(o2);
        }
        return;
    }

    // ---- standard epilogues ----
    #pragma unroll
    for (int mt = 0; mt < 4; mt++) {
        int r0 = m0 + wm * 64 + mt * 16 + gr;
        #pragma unroll
        for (int nt = 0; nt < 4; nt++) {
            int cc = n0 + wn * 32 + nt * 8 + gc2;
            float* p0 = C + (size_t)r0 * N + cc;
            float* p1 = p0 + (size_t)8 * N;
            float v0 = acc[mt][nt][0], v1 = acc[mt][nt][1];
            float v2 = acc[mt][nt][2], v3 = acc[mt][nt][3];
            if (EPI == 1) {
                float2 o0 = *(float2*)p0, o1 = *(float2*)p1;
                v0 += o0.x; v1 += o0.y; v2 += o1.x; v3 += o1.y;
            }
            if (EPI == 2) {
                v0 = to_tf32(gelu_tanh(v0)); v1 = to_tf32(gelu_tanh(v1));
                v2 = to_tf32(gelu_tanh(v2)); v3 = to_tf32(gelu_tanh(v3));
            }
            if (EPI == 3) {
                v0 = to_tf32(v0); v1 = to_tf32(v1);
                v2 = to_tf32(v2); v3 = to_tf32(v3);
            }
            *(float2*)p0 = make_float2(v0, v1);
            *(float2*)p1 = make_float2(v2, v3);
        }
    }
}

// =====================================================================
// Flash attention, tf32 mma.sync. CTA = (128 q-rows, head, batch).
// 256 threads, warp grid 2x4. K-tiles of 64 keys. Online softmax.
// smem: Q 64K | K 32K | VT 32K | P 32K | stats ~3K  = 166912 B
// =====================================================================
#define FAQ_OFF 0
#define FAK_OFF 65536
#define FAV_OFF 98304
#define FAP_OFF 131072
#define FAM_OFF 163840
#define FAL_OFF 164352
#define FAR_OFF 164864
#define FA_SMEM 166912

__global__ void __launch_bounds__(256) fattn_kernel(const float* __restrict__ qkv,
                                                    float* __restrict__ y) {
    extern __shared__ char smem[];
    uint32_t sb = smem_u32(smem);
    float* ms  = (float*)(smem + FAM_OFF);
    float* ls  = (float*)(smem + FAL_OFF);
    float* red = (float*)(smem + FAR_OFF);

    int qt = (int)gridDim.x - 1 - (int)blockIdx.x;   // big tiles first
    int h = blockIdx.y, b = blockIdx.z;
    int g = h >> 2;
    int q0 = qt * 128;
    int tid = threadIdx.x, lane = tid & 31, wid = tid >> 5;
    int wm = wid & 1, wn = wid >> 1;
    int gr = lane >> 2, gc2 = (lane & 3) * 2;
    const float scale = 0.08838834764831845f;

    const float* qbase = qkv + (size_t)(b * Tc) * QKVc + h * HSc;
    const float* kbase = qkv + (size_t)(b * Tc) * QKVc + (Hc + g) * HSc;
    const float* vbase = qkv + (size_t)(b * Tc) * QKVc + (Hc + Gc + g) * HSc;

    // ---- load Q tile (128 x 128 f32) into 4 k-subtiles ----
    #pragma unroll
    for (int i = 0; i < 16; i++) {
        int t = tid + i * 256;
        int r = t >> 5, ch = t & 31;
        int ksub = ch >> 3, within = ch & 7;
        cp16(sb + FAQ_OFF + ksub * 16384 + swz((uint32_t)(r * 128 + within * 16)),
             qbase + (size_t)(q0 + r) * QKVc + ch * 4);
    }
    asm volatile("cp.async.commit_group;" ::: "memory");

    if (tid < 128) { ms[tid] = -1e30f; ls[tid] = 0.f; }

    float oacc[4][4][4];
    #pragma unroll
    for (int i = 0; i < 4; i++)
        #pragma unroll
        for (int j = 0; j < 4; j++)
            #pragma unroll
            for (int r = 0; r < 4; r++) oacc[i][j][r] = 0.f;

    int rowA  = wm * 64 + (lane & 15);
    int khA   = lane >> 4;
    int rowBs = wn * 16 + ((lane & 16) >> 1) + (lane & 7);   // S-phase (n span 16)
    int rowBp = wn * 32 + ((lane & 16) >> 1) + (lane & 7);   // PV-phase (n span 32)
    int khB   = (lane >> 3) & 1;

    int nkt = 2 * qt + 2;
    for (int kt = 0; kt < nkt; kt++) {
        int s0 = kt * 64;
        if (kt > 0) __syncthreads();   // prior tile's PV ldsm done before overwrite

        // ---- load K tile (64 x 128) via cp.async ----
        #pragma unroll
        for (int i = 0; i < 8; i++) {
            int t = tid + i * 256;
            int r = t >> 5, ch = t & 31;
            int ksub = ch >> 3, within = ch & 7;
            cp16(sb + FAK_OFF + ksub * 8192 + swz((uint32_t)(r * 128 + within * 16)),
                 kbase + (size_t)(s0 + r) * QKVc + ch * 4);
        }
        asm volatile("cp.async.commit_group;" ::: "memory");

        // ---- load + transpose V tile: VT[j][s], 2 s-subtiles of [128][32] ----
        {
            int s = tid >> 2;            // 0..63
            int jc = (tid & 3) * 32;
            int ssub = s >> 5, swi = s & 31;
            const float* vr = vbase + (size_t)(s0 + s) * QKVc + jc;
            #pragma unroll
            for (int i = 0; i < 8; i++) {
                float4 v4 = *(const float4*)(vr + i * 4);
                int j = jc + i * 4;
                char* base = smem + FAV_OFF + ssub * 16384;
                *(float*)(base + swz((uint32_t)((j    ) * 128 + swi * 4))) = v4.x;
                *(float*)(base + swz((uint32_t)((j + 1) * 128 + swi * 4))) = v4.y;
                *(float*)(base + swz((uint32_t)((j + 2) * 128 + swi * 4))) = v4.z;
                *(float*)(base + swz((uint32_t)((j + 3) * 128 + swi * 4))) = v4.w;
            }
        }
        asm volatile("cp.async.wait_group 0;" ::: "memory");
        __syncthreads();

        // ---- S = Q K^T (128 x 64), warp tile 64x16 ----
        float sacc[4][2][4];
        #pragma unroll
        for (int i = 0; i < 4; i++)
            #pragma unroll
            for (int j = 0; j < 2; j++)
                #pragma unroll
                for (int r = 0; r < 4; r++) sacc[i][j][r] = 0.f;

        #pragma unroll
        for (int ks = 0; ks < 16; ks++) {
            uint32_t bqk0, bqk1, bqk2, bqk3;
            ldsm4(bqk0, bqk1, bqk2, bqk3,
                  sb + FAK_OFF + (ks >> 2) * 8192 +
                  swz((uint32_t)(rowBs * 128 + (ks & 3) * 32 + khB * 16)));
            #pragma unroll
            for (int mt = 0; mt < 4; mt++) {
                uint32_t a0, a1, a2, a3;
                ldsm4(a0, a1, a2, a3,
                      sb + FAQ_OFF + (ks >> 2) * 16384 +
                      swz((uint32_t)((rowA + mt * 16) * 128 + (ks & 3) * 32 + khA * 16)));
                mma_tf32(sacc[mt][0], a0, a1, a2, a3, bqk0, bqk1);
                mma_tf32(sacc[mt][1], a0, a1, a2, a3, bqk2, bqk3);
            }
        }

        // ---- scale + causal mask ----
        bool diag = (s0 >= q0);
        #pragma unroll
        for (int mt = 0; mt < 4; mt++)
            #pragma unroll
            for (int nt = 0; nt < 2; nt++)
                #pragma unroll
                for (int idx = 0; idx < 4; idx++) {
                    float v = sacc[mt][nt][idx] * scale;
                    if (diag) {
                        int rg = q0 + wm * 64 + mt * 16 + gr + ((idx >> 1) << 3);
                        int sg = s0 + wn * 16 + nt * 8 + gc2 + (idx & 1);
                        if (sg > rg) v = -1e30f;
                    }
                    sacc[mt][nt][idx] = v;
                }

        // ---- row max reduce ----
        #pragma unroll
        for (int mt = 0; mt < 4; mt++)
            #pragma unroll
            for (int hh = 0; hh < 2; hh++) {
                float mx = fmaxf(fmaxf(sacc[mt][0][hh * 2], sacc[mt][0][hh * 2 + 1]),
                                 fmaxf(sacc[mt][1][hh * 2], sacc[mt][1][hh * 2 + 1]));
                mx = fmaxf(mx, __shfl_xor_sync(0xffffffffu, mx, 1));
                mx = fmaxf(mx, __shfl_xor_sync(0xffffffffu, mx, 2));
                if ((lane & 3) == 0)
                    red[wn * 128 + wm * 64 + mt * 16 + gr + hh * 8] = mx;
            }
        __syncthreads();

        float mnewr[4][2], alpha[4][2], psum[4][2];
        #pragma unroll
        for (int mt = 0; mt < 4; mt++)
            #pragma unroll
            for (int hh = 0; hh < 2; hh++) {
                int r = wm * 64 + mt * 16 + gr + hh * 8;
                float tmax = fmaxf(fmaxf(red[r], red[128 + r]),
                                   fmaxf(red[256 + r], red[384 + r]));
                float mold = ms[r];
                float mnew = fmaxf(mold, tmax);
                mnewr[mt][hh] = mnew;
                alpha[mt][hh] = expf(mold - mnew);
                float p0 = expf(sacc[mt][0][hh * 2]     - mnew);
                float p1 = expf(sacc[mt][0][hh * 2 + 1] - mnew);
                float p2 = expf(sacc[mt][1][hh * 2]     - mnew);
                float p3 = expf(sacc[mt][1][hh * 2 + 1] - mnew);
                sacc[mt][0][hh * 2]     = p0; sacc[mt][0][hh * 2 + 1] = p1;
                sacc[mt][1][hh * 2]     = p2; sacc[mt][1][hh * 2 + 1] = p3;
                float ps = p0 + p1 + p2 + p3;
                ps += __shfl_xor_sync(0xffffffffu, ps, 1);
                ps += __shfl_xor_sync(0xffffffffu, ps, 2);
                psum[mt][hh] = ps;
            }
        __syncthreads();   // all reads of red done before overwrite
        #pragma unroll
        for (int mt = 0; mt < 4; mt++)
            #pragma unroll
            for (int hh = 0; hh < 2; hh++)
                if ((lane & 3) == 0)
                    red[wn * 128 + wm * 64 + mt * 16 + gr + hh * 8] = psum[mt][hh];
        __syncthreads();
        #pragma unroll
        for (int mt = 0; mt < 4; mt++)
            #pragma unroll
            for (int hh = 0; hh < 2; hh++) {
                int r = wm * 64 + mt * 16 + gr + hh * 8;
                float pt = red[r] + red[128 + r] + red[256 + r] + red[384 + r];
                float lnew = ls[r] * alpha[mt][hh] + pt;
                if (wn == 0 && (lane & 3) == 0) { ms[r] = mnewr[mt][hh]; ls[r] = lnew; }
            }

        // ---- store P (tf32) to smem; rescale O ----
        #pragma unroll
        for (int mt = 0; mt < 4; mt++)
            #pragma unroll
            for (int nt = 0; nt < 2; nt++) {
                int c = wn * 16 + nt * 8 + gc2;
                int ssub = c >> 5, cw = c & 31;
                int r0l = wm * 64 + mt * 16 + gr;
                char* base = smem + FAP_OFF + ssub * 16384;
                *(float2*)(base + swz((uint32_t)(r0l * 128 + cw * 4))) =
                    make_float2(to_tf32(sacc[mt][nt][0]), to_tf32(sacc[mt][nt][1]));
                *(float2*)(base + swz((uint32_t)((r0l + 8) * 128 + cw * 4))) =
                    make_float2(to_tf32(sacc[mt][nt][2]), to_tf32(sacc[mt][nt][3]));
            }
        #pragma unroll
        for (int mt = 0; mt < 4; mt++)
            #pragma unroll
            for (int nt = 0; nt < 4; nt++) {
                oacc[mt][nt][0] *= alpha[mt][0];
                oacc[mt][nt][1] *= alpha[mt][0];
                oacc[mt][nt][2] *= alpha[mt][1];
                oacc[mt][nt][3] *= alpha[mt][1];
            }
        __syncthreads();   // P visible to all warps

        // ---- O += P V  (P 128x64, V^T in smem) ----
        #pragma unroll
        for (int ks = 0; ks < 8; ks++) {
            uint32_t vb0[4], vb1[4];
            {
                uint32_t r0, r1, r2, r3;
                ldsm4(r0, r1, r2, r3,
                      sb + FAV_OFF + (ks >> 2) * 16384 +
                      swz((uint32_t)(rowBp * 128 + (ks & 3) * 32 + khB * 16)));
                vb0[0] = r0; vb1[0] = r1; vb0[1] = r2; vb1[1] = r3;
                ldsm4(r0, r1, r2, r3,
                      sb + FAV_OFF + (ks >> 2) * 16384 +
                      swz((uint32_t)((rowBp + 16) * 128 + (ks & 3) * 32 + khB * 16)));
                vb0[2] = r0; vb1[2] = r1; vb0[3] = r2; vb1[3] = r3;
            }
            #pragma unroll
            for (int mt = 0; mt < 4; mt++) {
                uint32_t a0, a1, a2, a3;
                ldsm4(a0, a1, a2, a3,
                      sb + FAP_OFF + (ks >> 2) * 16384 +
                      swz((uint32_t)((rowA + mt * 16) * 128 + (ks & 3) * 32 + khA * 16)));
                #pragma unroll
                for (int nt = 0; nt < 4; nt++)
                    mma_tf32(oacc[mt][nt], a0, a1, a2, a3, vb0[nt], vb1[nt]);
            }
        }
    }

    __syncthreads();   // final ls visible
    #pragma unroll
    for (int mt = 0; mt < 4; mt++) {
        int rl = wm * 64 + mt * 16 + gr;
        float i0 = 1.f / ls[rl];
        float i1 = 1.f / ls[rl + 8];
        int rg = q0 + rl;
        #pragma unroll
        for (int nt = 0; nt < 4; nt++) {
            int j = h * HSc + wn * 32 + nt * 8 + gc2;
            *(float2*)&y[(size_t)(b * Tc + rg) * (Hc * HSc) + j] =
                make_float2(to_tf32(oacc[mt][nt][0] * i0), to_tf32(oacc[mt][nt][1] * i0));
            *(float2*)&y[(size_t)(b * Tc + rg + 8) * (Hc * HSc) + j] =
                make_float2(to_tf32(oacc[mt][nt][2] * i1), to_tf32(oacc[mt][nt][3] * i1));
        }
    }
}

// ---------------- weight round-to-tf32 (two arrays per launch) ----------------
__global__ void round_w2_kernel(const float* __restrict__ in1, float* __restrict__ out1, size_t n1,
                                const float* __restrict__ in2, float* __restrict__ out2, size_t n2) {
    size_t i = (size_t)blockIdx.x * blockDim.x + threadIdx.x;
    const float* in; float* out; size_t j;
    if (i < n1) { in = in1; out = out1; j = i; }
    else if (i < n1 + n2) { in = in2; out = out2; j = i - n1; }
    else return;
    float4 v = ((const float4*)in)[j];
    v.x = to_tf32(v.x); v.y = to_tf32(v.y); v.z = to_tf32(v.z); v.w = to_tf32(v.w);
    ((float4*)out)[j] = v;
}

__global__ void round_w_kernel(const float* __restrict__ in, float* __restrict__ out, size_t n4) {
    size_t i = (size_t)blockIdx.x * blockDim.x + threadIdx.x;
    if (i < n4) {
        float4 v = ((const float4*)in)[i];
        v.x = to_tf32(v.x); v.y = to_tf32(v.y); v.z = to_tf32(v.z); v.w = to_tf32(v.w);
        ((float4*)out)[i] = v;
    }
}

// ---------------- embed ----------------
__global__ void embed_kernel(const int* __restrict__ idx,
                             const float* __restrict__ wte,
                             float* __restrict__ x) {
    size_t i = (size_t)blockIdx.x * blockDim.x + threadIdx.x;
    if (i < (size_t)NTc * Ec) {
        int tok = (int)(i / Ec);
        int e   = (int)(i % Ec);
        x[i] = wte[(size_t)idx[tok] * Ec + e];
    }
}

// ---------------- rmsnorm (block per token, float4), output rounded to tf32 ------
__global__ void __launch_bounds__(256) rmsnorm_kernel(const float* __restrict__ x,
                                                      const float* __restrict__ w,
                                                      float* __restrict__ out) {
    int t = blockIdx.x;
    const float4* xr = (const float4*)(x + (size_t)t * Ec);
    const float4* wr = (const float4*)w;
    float4* orow = (float4*)(out + (size_t)t * Ec);
    float4 xv[2], wv[2];
    float s = 0.f;
    #pragma unroll
    for (int i = 0; i < 2; i++) {
        xv[i] = xr[threadIdx.x + i * 256];
        wv[i] = wr[threadIdx.x + i * 256];
        s += xv[i].x * xv[i].x + xv[i].y * xv[i].y + xv[i].z * xv[i].z + xv[i].w * xv[i].w;
    }
    __shared__ float sh[8];
    int lane = threadIdx.x & 31, warp = threadIdx.x >> 5;
    #pragma unroll
    for (int o = 16; o > 0; o >>= 1) s += __shfl_xor_sync(0xffffffffu, s, o);
    if (lane == 0) sh[warp] = s;
    __syncthreads();
    float tot = sh[0] + sh[1] + sh[2] + sh[3] + sh[4] + sh[5] + sh[6] + sh[7];
    float inv = rsqrtf(tot / (float)Ec + EPSc);
    #pragma unroll
    for (int i = 0; i < 2; i++) {
        float4 o;
        o.x = to_tf32(xv[i].x * inv * wv[i].x);
        o.y = to_tf32(xv[i].y * inv * wv[i].y);
        o.z = to_tf32(xv[i].z * inv * wv[i].z);
        o.w = to_tf32(xv[i].w * inv * wv[i].w);
        orow[threadIdx.x + i * 256] = o;
    }
}

// ---------------- launcher ----------------
static void launch_gemm(int epi, const float* A, const float* W, float* C,
                        int M, int N, int K) {
    dim3 grid(N / GBN, M / GBM);
    if (epi == 0)      tc_gemm<0><<<grid, 256, GEMM_SMEM>>>(A, W, C, M, N, K);
    else if (epi == 1) tc_gemm<1><<<grid, 256, GEMM_SMEM>>>(A, W, C, M, N, K);
    else if (epi == 2) tc_gemm<2><<<grid, 256, GEMM_SMEM>>>(A, W, C, M, N, K);
    else if (epi == 3) tc_gemm<3><<<grid, 256, GEMM_SMEM>>>(A, W, C, M, N, K);
    else               tc_gemm<4><<<grid, 256, GEMM_SMEM>>>(A, W, C, M, N, K);
}

extern "C" void kernel_launch(void* const* d_in, const int* in_sizes, int n_in,
                              void* d_out, int out_size) {
    const int*   idx  = (const int*)  d_in[0];
    const float* wte  = (const float*)d_in[1];
    const float* qkvw = (const float*)d_in[2];
    const float* apw  = (const float*)d_in[3];
    const float* fcw  = (const float*)d_in[4];
    const float* mpw  = (const float*)d_in[5];
    const float* n1w  = (const float*)d_in[6];
    const float* n2w  = (const float*)d_in[7];
    const float* lnfw = (const float*)d_in[8];
    const float* lmw  = (const float*)d_in[9];
    float* out = (float*)d_out;
    (void)in_sizes; (void)n_in; (void)out_size;

    float *x, *xn, *qkv, *att, *ffh;
    float *wq, *wa, *wf, *wm, *wl;
    cudaGetSymbolAddress((void**)&x,   g_x);
    cudaGetSymbolAddress((void**)&xn,  g_xn);
    cudaGetSymbolAddress((void**)&qkv, g_qkv);
    cudaGetSymbolAddress((void**)&att, g_att);
    cudaGetSymbolAddress((void**)&ffh, g_ffh);
    cudaGetSymbolAddress((void**)&wq,  g_wqkv);
    cudaGetSymbolAddress((void**)&wa,  g_wap);
    cudaGetSymbolAddress((void**)&wf,  g_wfc);
    cudaGetSymbolAddress((void**)&wm,  g_wmp);
    cudaGetSymbolAddress((void**)&wl,  g_wlm);

    cudaFuncSetAttribute(tc_gemm<0>, cudaFuncAttributeMaxDynamicSharedMemorySize, GEMM_SMEM);
    cudaFuncSetAttribute(tc_gemm<1>, cudaFuncAttributeMaxDynamicSharedMemorySize, GEMM_SMEM);
    cudaFuncSetAttribute(tc_gemm<2>, cudaFuncAttributeMaxDynamicSharedMemorySize, GEMM_SMEM);
    cudaFuncSetAttribute(tc_gemm<3>, cudaFuncAttributeMaxDynamicSharedMemorySize, GEMM_SMEM);
    cudaFuncSetAttribute(tc_gemm<4>, cudaFuncAttributeMaxDynamicSharedMemorySize, GEMM_SMEM);
    cudaFuncSetAttribute(fattn_kernel, cudaFuncAttributeMaxDynamicSharedMemorySize, FA_SMEM);

    // weight rounding
    {
        size_t n1 = (size_t)Lc * QKVc * Ec / 4;
        size_t n2 = (size_t)Lc * Ec * Hc * HSc / 4;
        round_w2_kernel<<<(unsigned)((n1 + n2 + 255) / 256), 256>>>(qkvw, wq, n1, apw, wa, n2);
        size_t n3 = (size_t)Lc * FFc * Ec / 4;
        size_t n4 = (size_t)Lc * Ec * FFc / 4;
        round_w2_kernel<<<(unsigned)((n3 + n4 + 255) / 256), 256>>>(fcw, wf, n3, mpw, wm, n4);
        size_t n5 = (size_t)Vc * Ec / 4;
        round_w_kernel<<<(unsigned)((n5 + 255) / 256), 256>>>(lmw, wl, n5);
    }

    embed_kernel<<<((size_t)NTc * Ec + 255) / 256, 256>>>(idx, wte, x);

    for (int l = 0; l < Lc; l++) {
        rmsnorm_kernel<<<NTc, 256>>>(x, n1w + (size_t)l * Ec, xn);
        launch_gemm(4, xn, wq + (size_t)l * QKVc * Ec, qkv, NTc, QKVc, Ec);  // fused rope
        fattn_kernel<<<dim3(Tc / 128, Hc, Bc), 256, FA_SMEM>>>(qkv, att);
        launch_gemm(1, att, wa + (size_t)l * Ec * (Hc * HSc), x, NTc, Ec, Hc * HSc);
        rmsnorm_kernel<<<NTc, 256>>>(x, n2w + (size_t)l * Ec, xn);
        launch_gemm(2, xn, wf + (size_t)l * FFc * Ec, ffh, NTc, FFc, Ec);
        launch_gemm(1, ffh, wm + (size_t)l * Ec * FFc, x, NTc, Ec, FFc);
    }

    rmsnorm_kernel<<<NTc, 256>>>(x, lnfw, xn);
    launch_gemm(0, xn, wl, out, NTc, Vc, Ec);
}